// round 14
// baseline (speedup 1.0000x reference)
#include <cuda_runtime.h>

#define BB 8
#define LL 1024
#define DD 512
#define HD 4096

// Accumulators. Zero at module load (first call OK); k4's epilogue re-zeroes
// xsum2/vsum4 for the next replay; zc re-zeroed by kA's extra blocks each call.
__device__ __align__(16) float g_xsum2[2][BB * DD];   // 32 KB
__device__ __align__(16) float g_vsum4[4][BB * HD];   // 512 KB
__device__ __align__(16) float g_zc[4][BB * DD];      // 64 KB
__device__ __align__(16) float g_z[BB * DD];          // merged z (k3b output)

__device__ __forceinline__ void red_add_v4(float* a, float4 v) {
    asm volatile("red.global.add.v4.f32 [%0], {%1,%2,%3,%4};"
                 :: "l"(a), "f"(v.x), "f"(v.y), "f"(v.z), "f"(v.w) : "memory");
}

__device__ __forceinline__ unsigned smem_u32(const void* p) {
    return (unsigned)__cvta_generic_to_shared(p);
}
__device__ __forceinline__ void mbar_init(unsigned mbar, unsigned cnt) {
    asm volatile("mbarrier.init.shared.b64 [%0], %1;" :: "r"(mbar), "r"(cnt) : "memory");
}
__device__ __forceinline__ void mbar_expect_tx(unsigned mbar, unsigned bytes) {
    asm volatile("mbarrier.arrive.expect_tx.shared.b64 _, [%0], %1;"
                 :: "r"(mbar), "r"(bytes) : "memory");
}
__device__ __forceinline__ void bulk_g2s(unsigned dst, const void* src, unsigned bytes,
                                         unsigned mbar) {
    asm volatile("cp.async.bulk.shared::cluster.global.mbarrier::complete_tx::bytes "
                 "[%0], [%1], %2, [%3];"
                 :: "r"(dst), "l"(src), "r"(bytes), "r"(mbar) : "memory");
}
__device__ __forceinline__ void fence_async() {
    asm volatile("fence.proxy.async.shared::cta;" ::: "memory");
}
__device__ __forceinline__ void mbar_wait0(unsigned mbar) {
    asm volatile(
        "{\n\t.reg .pred P;\n\t"
        "WL_%=:\n\t"
        "mbarrier.try_wait.parity.acquire.cta.shared::cta.b64 P, [%0], 0, 0x989680;\n\t"
        "@P bra.uni WD_%=;\n\t"
        "bra.uni WL_%=;\n\t"
        "WD_%=:\n\t}"
        :: "r"(mbar) : "memory");
}

// kA: blocks [0,512): xsum += input over 16-row chunks (red into 2 copies).
//     blocks [512,528): zero g_zc (4096 quads) for this call.
__global__ __launch_bounds__(256) void kA(const float* __restrict__ x) {
    cudaTriggerProgrammaticLaunchCompletion();
    int blk = blockIdx.x, t = threadIdx.x;
    if (blk >= 512) {
        int q = (blk - 512) * 256 + t;   // 4096 quads
        reinterpret_cast<float4*>(&g_zc[0][0])[q] = make_float4(0.f, 0.f, 0.f, 0.f);
        return;
    }
    int b = blk >> 6, c = blk & 63;
    int h = t >> 7, q = t & 127;
    const float4* p = reinterpret_cast<const float4*>(x)
                    + (size_t)b * LL * 128 + (size_t)(c * 16 + h * 8) * 128 + q;
    float4 s = make_float4(0.f, 0.f, 0.f, 0.f);
#pragma unroll
    for (int r = 0; r < 8; ++r) {
        float4 v = p[r * 128];
        s.x += v.x; s.y += v.y; s.z += v.z; s.w += v.w;
    }
    red_add_v4(&g_xsum2[h][b * DD + 4 * q], s);
}

// k2: vsum += xsum @ wv (+ L*bv on kc==0).
// Weight tile staged by cp.async.bulk (16 x 2KB row copies, DMA path) — issued
// BEFORE the dependency sync so the transfer overlaps kA + the wait.
__global__ void k2_vsum(const float* __restrict__ wv, const float* __restrict__ bv) {
    cudaTriggerProgrammaticLaunchCompletion();
    __shared__ float4 sw[16 * 128];   // 32 KB weight tile
    __shared__ float4 sc[256 * 4];    // 16 KB; bytes [0,512)=xs, [512,520)=mbar
    float* xs = reinterpret_cast<float*>(sc);
    unsigned mbar = smem_u32(reinterpret_cast<char*>(sc) + 512);

    int t = threadIdx.x;
    int jb = blockIdx.x, kc = blockIdx.y;
    int k0 = kc * 16;

    if (t == 0) mbar_init(mbar, 1);
    __syncthreads();
    if (t == 0) {
        fence_async();
        mbar_expect_tx(mbar, 16 * 2048);
        const float* src0 = wv + (size_t)k0 * HD + jb * 512;
        unsigned dst0 = smem_u32(sw);
#pragma unroll
        for (int kk = 0; kk < 16; ++kk)
            bulk_g2s(dst0 + kk * 2048, src0 + (size_t)kk * HD, 2048, mbar);
    }

    cudaGridDependencySynchronize();             // kA's reds now visible

    if (t < 128) {
        int b = t >> 4, kk = t & 15;
        int a = b * DD + k0 + kk;
        xs[t] = g_xsum2[0][a] + g_xsum2[1][a];
    }
    __syncthreads();                             // xs visible to all
    mbar_wait0(mbar);                            // weight tile resident

    int jq = t & 127, kg = (t >> 7) & 1, bg = t >> 8;
    float4 acc[4];
#pragma unroll
    for (int i = 0; i < 4; ++i) acc[i] = make_float4(0.f, 0.f, 0.f, 0.f);
#pragma unroll
    for (int kk = 0; kk < 8; ++kk) {
        float4 wq = sw[(kg * 8 + kk) * 128 + jq];
#pragma unroll
        for (int bi = 0; bi < 4; ++bi) {
            float xv = xs[(bg * 4 + bi) * 16 + kg * 8 + kk];
            acc[bi].x += xv * wq.x; acc[bi].y += xv * wq.y;
            acc[bi].z += xv * wq.z; acc[bi].w += xv * wq.w;
        }
    }
    __syncthreads();                 // all waiters past mbar; sc reuse is safe
    int slot = (bg * 128 + jq) * 4;
    if (kg == 1) {
#pragma unroll
        for (int bi = 0; bi < 4; ++bi) sc[slot + bi] = acc[bi];
    }
    __syncthreads();
    if (kg == 0) {
        float4 lb = make_float4(0.f, 0.f, 0.f, 0.f);
        if (kc == 0) {
            float4 bv4 = reinterpret_cast<const float4*>(bv)[jb * 128 + jq];
            lb.x = 1024.f * bv4.x; lb.y = 1024.f * bv4.y;
            lb.z = 1024.f * bv4.z; lb.w = 1024.f * bv4.w;
        }
        float* base = &g_vsum4[kc & 3][0];
#pragma unroll
        for (int bi = 0; bi < 4; ++bi) {
            float4 o = sc[slot + bi];
            o.x += acc[bi].x + lb.x; o.y += acc[bi].y + lb.y;
            o.z += acc[bi].z + lb.z; o.w += acc[bi].w + lb.w;
            red_add_v4(base + (bg * 4 + bi) * HD + jb * 512 + 4 * jq, o);
        }
    }
}

// k3: zc += vsum @ fc_w (+ fc_b on jc==0).  Tile is 32KB CONTIGUOUS in gmem
// (16 full rows of fc_w) — one cp.async.bulk.
__global__ void k3_z(const float* __restrict__ fcw, const float* __restrict__ fcb) {
    cudaTriggerProgrammaticLaunchCompletion();
    __shared__ float4 sw[16 * 128];
    __shared__ float4 sc[256 * 4];
    float* vs = reinterpret_cast<float*>(sc);
    unsigned mbar = smem_u32(reinterpret_cast<char*>(sc) + 512);

    int t = threadIdx.x;
    int jc = blockIdx.x;
    int j0 = jc * 16;

    if (t == 0) mbar_init(mbar, 1);
    __syncthreads();
    if (t == 0) {
        fence_async();
        mbar_expect_tx(mbar, 32768);
        bulk_g2s(smem_u32(sw), fcw + (size_t)j0 * DD, 32768, mbar);
    }

    cudaGridDependencySynchronize();             // k2's reds now visible

    if (t < 128) {
        int b = t >> 4, jj = t & 15;
        int a = b * HD + j0 + jj;
        vs[t] = g_vsum4[0][a] + g_vsum4[1][a] + g_vsum4[2][a] + g_vsum4[3][a];
    }
    __syncthreads();
    mbar_wait0(mbar);

    int iq = t & 127, jg = (t >> 7) & 1, bg = t >> 8;
    float4 acc[4];
#pragma unroll
    for (int i = 0; i < 4; ++i) acc[i] = make_float4(0.f, 0.f, 0.f, 0.f);
#pragma unroll
    for (int jj = 0; jj < 8; ++jj) {
        float4 wq = sw[(jg * 8 + jj) * 128 + iq];
#pragma unroll
        for (int bi = 0; bi < 4; ++bi) {
            float vv = vs[(bg * 4 + bi) * 16 + jg * 8 + jj];
            acc[bi].x += vv * wq.x; acc[bi].y += vv * wq.y;
            acc[bi].z += vv * wq.z; acc[bi].w += vv * wq.w;
        }
    }
    __syncthreads();
    int slot = (bg * 128 + iq) * 4;
    if (jg == 1) {
#pragma unroll
        for (int bi = 0; bi < 4; ++bi) sc[slot + bi] = acc[bi];
    }
    __syncthreads();
    if (jg == 0) {
        float4 fb = make_float4(0.f, 0.f, 0.f, 0.f);
        if (jc == 0) fb = reinterpret_cast<const float4*>(fcb)[iq];
        float* base = &g_zc[jc & 3][0];
#pragma unroll
        for (int bi = 0; bi < 4; ++bi) {
            float4 o = sc[slot + bi];
            o.x += acc[bi].x + fb.x; o.y += acc[bi].y + fb.y;
            o.z += acc[bi].z + fb.z; o.w += acc[bi].w + fb.w;
            red_add_v4(base + (bg * 4 + bi) * DD + 4 * iq, o);
        }
    }
}

// k3b: merge zc[4] -> g_z. Tiny PDL link kernel — hidden under k4's prologue.
__global__ void k3b_merge() {
    cudaTriggerProgrammaticLaunchCompletion();
    cudaGridDependencySynchronize();
    int q = blockIdx.x * 512 + threadIdx.x;      // 1024 quads / 2 blocks
    float4 s = make_float4(0.f, 0.f, 0.f, 0.f);
#pragma unroll
    for (int c = 0; c < 4; ++c) {
        float4 v = reinterpret_cast<const float4*>(&g_zc[c][0])[q];
        s.x += v.x; s.y += v.y; s.z += v.z; s.w += v.w;
    }
    reinterpret_cast<float4*>(g_z)[q] = s;
}

// k4: out = LayerNorm(g_z[b] + x[b,l]) * g + beta.
__global__ __launch_bounds__(256, 4) void k4_ln(
        const float* __restrict__ x,
        const float* __restrict__ lng, const float* __restrict__ lnb,
        float* __restrict__ out) {
    __shared__ float4 zs[128];
    __shared__ float4 gs[128];
    __shared__ float4 bs[128];
    int t = threadIdx.x, blk = blockIdx.x;
    int b = blk >> 6;

    int warp = t >> 5, lane = t & 31;
    int row0 = blk * 16 + warp * 2;
    const float4* xp0 = reinterpret_cast<const float4*>(x) + (size_t)row0 * 128;
    const float4* xp1 = xp0 + 128;

    float4 xa[4], xb[4];
#pragma unroll
    for (int i = 0; i < 4; ++i) xa[i] = xp0[lane + 32 * i];
#pragma unroll
    for (int i = 0; i < 4; ++i) xb[i] = xp1[lane + 32 * i];
    if (t >= 128) {
        int u = t - 128;
        gs[u] = reinterpret_cast<const float4*>(lng)[u];
        bs[u] = reinterpret_cast<const float4*>(lnb)[u];
    }

    cudaGridDependencySynchronize();

    if (t < 128)
        zs[t] = reinterpret_cast<const float4*>(g_z)[b * 128 + t];
    __syncthreads();

    float sa = 0.f, qa = 0.f, sb = 0.f, qb = 0.f;
#pragma unroll
    for (int i = 0; i < 4; ++i) {
        float4 z = zs[lane + 32 * i];
        float y;
        y = xa[i].x + z.x; sa += y; qa += y * y;
        y = xa[i].y + z.y; sa += y; qa += y * y;
        y = xa[i].z + z.z; sa += y; qa += y * y;
        y = xa[i].w + z.w; sa += y; qa += y * y;
        y = xb[i].x + z.x; sb += y; qb += y * y;
        y = xb[i].y + z.y; sb += y; qb += y * y;
        y = xb[i].z + z.z; sb += y; qb += y * y;
        y = xb[i].w + z.w; sb += y; qb += y * y;
    }
#pragma unroll
    for (int o = 16; o > 0; o >>= 1) {
        sa += __shfl_xor_sync(0xFFFFFFFFu, sa, o);
        qa += __shfl_xor_sync(0xFFFFFFFFu, qa, o);
        sb += __shfl_xor_sync(0xFFFFFFFFu, sb, o);
        qb += __shfl_xor_sync(0xFFFFFFFFu, qb, o);
    }
    float mua  = sa * (1.0f / DD);
    float inva = rsqrtf(qa * (1.0f / DD) - mua * mua + 1e-5f);
    float mub  = sb * (1.0f / DD);
    float invb = rsqrtf(qb * (1.0f / DD) - mub * mub + 1e-5f);

    float4* op0 = reinterpret_cast<float4*>(out) + (size_t)row0 * 128;
    float4* op1 = op0 + 128;
#pragma unroll
    for (int i = 0; i < 4; ++i) {
        float4 z  = zs[lane + 32 * i];
        float4 gv = gs[lane + 32 * i];
        float4 be = bs[lane + 32 * i];
        float4 o;
        o.x = (xa[i].x + z.x - mua) * inva * gv.x + be.x;
        o.y = (xa[i].y + z.y - mua) * inva * gv.y + be.y;
        o.z = (xa[i].z + z.z - mua) * inva * gv.z + be.z;
        o.w = (xa[i].w + z.w - mua) * inva * gv.w + be.w;
        op0[lane + 32 * i] = o;
        o.x = (xb[i].x + z.x - mub) * invb * gv.x + be.x;
        o.y = (xb[i].y + z.y - mub) * invb * gv.y + be.y;
        o.z = (xb[i].z + z.z - mub) * invb * gv.z + be.z;
        o.w = (xb[i].w + z.w - mub) * invb * gv.w + be.w;
        op1[lane + 32 * i] = o;
    }

    float4 z4 = make_float4(0.f, 0.f, 0.f, 0.f);
    if (t < 64)
        reinterpret_cast<float4*>(&g_vsum4[0][0])[blk * 64 + t] = z4;
    if (t < 4)
        reinterpret_cast<float4*>(&g_xsum2[0][0])[blk * 4 + t] = z4;
}

extern "C" void kernel_launch(void* const* d_in, const int* in_sizes, int n_in,
                              void* d_out, int out_size) {
    const float* input = (const float*)d_in[0];
    const float* wv    = (const float*)d_in[5];
    const float* bv    = (const float*)d_in[6];
    const float* fcw   = (const float*)d_in[9];
    const float* fcb   = (const float*)d_in[10];
    const float* lng   = (const float*)d_in[11];
    const float* lnb   = (const float*)d_in[12];
    float* out = (float*)d_out;

    kA<<<528, 256>>>(input);

    cudaLaunchAttribute attr[1];
    attr[0].id = cudaLaunchAttributeProgrammaticStreamSerialization;
    attr[0].val.programmaticStreamSerializationAllowed = 1;

    {
        cudaLaunchConfig_t cfg{};
        cfg.gridDim = dim3(8, 32); cfg.blockDim = dim3(512);
        cfg.attrs = attr; cfg.numAttrs = 1; cfg.stream = 0;
        cudaLaunchKernelEx(&cfg, k2_vsum, wv, bv);
    }
    {
        cudaLaunchConfig_t cfg{};
        cfg.gridDim = dim3(256); cfg.blockDim = dim3(512);
        cfg.attrs = attr; cfg.numAttrs = 1; cfg.stream = 0;
        cudaLaunchKernelEx(&cfg, k3_z, fcw, fcb);
    }
    {
        cudaLaunchConfig_t cfg{};
        cfg.gridDim = dim3(2); cfg.blockDim = dim3(512);
        cfg.attrs = attr; cfg.numAttrs = 1; cfg.stream = 0;
        cudaLaunchKernelEx(&cfg, k3b_merge);
    }
    {
        cudaLaunchConfig_t cfg{};
        cfg.gridDim = dim3(512); cfg.blockDim = dim3(256);
        cfg.attrs = attr; cfg.numAttrs = 1; cfg.stream = 0;
        cudaLaunchKernelEx(&cfg, k4_ln, input, lng, lnb, out);
    }
}

// round 15
// speedup vs baseline: 1.0923x; 1.0923x over previous
#include <cuda_runtime.h>

#define BB 8
#define LL 1024
#define DD 512
#define HD 4096

// Accumulators. Zero at module load (first call OK); k4's epilogue re-zeroes
// xsum2/vsum4 for the next replay; zc re-zeroed by kA's extra blocks each call.
__device__ __align__(16) float g_xsum2[2][BB * DD];   // 32 KB
__device__ __align__(16) float g_vsum4[4][BB * HD];   // 512 KB
__device__ __align__(16) float g_zc[4][BB * DD];      // 64 KB
__device__ __align__(16) float g_z[BB * DD];          // merged z (k3b output)

__device__ __forceinline__ void red_add_v4(float* a, float4 v) {
    asm volatile("red.global.add.v4.f32 [%0], {%1,%2,%3,%4};"
                 :: "l"(a), "f"(v.x), "f"(v.y), "f"(v.z), "f"(v.w) : "memory");
}

__device__ __forceinline__ unsigned smem_u32(const void* p) {
    return (unsigned)__cvta_generic_to_shared(p);
}
__device__ __forceinline__ void mbar_init(unsigned mbar, unsigned cnt) {
    asm volatile("mbarrier.init.shared.b64 [%0], %1;" :: "r"(mbar), "r"(cnt) : "memory");
}
__device__ __forceinline__ void mbar_expect_tx(unsigned mbar, unsigned bytes) {
    asm volatile("mbarrier.arrive.expect_tx.shared.b64 _, [%0], %1;"
                 :: "r"(mbar), "r"(bytes) : "memory");
}
__device__ __forceinline__ void bulk_g2s(unsigned dst, const void* src, unsigned bytes,
                                         unsigned mbar) {
    asm volatile("cp.async.bulk.shared::cluster.global.mbarrier::complete_tx::bytes "
                 "[%0], [%1], %2, [%3];"
                 :: "r"(dst), "l"(src), "r"(bytes), "r"(mbar) : "memory");
}
__device__ __forceinline__ void fence_async() {
    asm volatile("fence.proxy.async.shared::cta;" ::: "memory");
}
__device__ __forceinline__ void mbar_wait0(unsigned mbar) {
    asm volatile(
        "{\n\t.reg .pred P;\n\t"
        "WL_%=:\n\t"
        "mbarrier.try_wait.parity.acquire.cta.shared::cta.b64 P, [%0], 0, 0x989680;\n\t"
        "@P bra.uni WD_%=;\n\t"
        "bra.uni WL_%=;\n\t"
        "WD_%=:\n\t}"
        :: "r"(mbar) : "memory");
}

// kA: blocks [0,512): xsum += input over 16-row chunks (red into 2 copies).
//     blocks [512,528): zero g_zc (4096 quads) for this call.
__global__ __launch_bounds__(256) void kA(const float* __restrict__ x) {
    cudaTriggerProgrammaticLaunchCompletion();
    int blk = blockIdx.x, t = threadIdx.x;
    if (blk >= 512) {
        int q = (blk - 512) * 256 + t;
        reinterpret_cast<float4*>(&g_zc[0][0])[q] = make_float4(0.f, 0.f, 0.f, 0.f);
        return;
    }
    int b = blk >> 6, c = blk & 63;
    int h = t >> 7, q = t & 127;
    const float4* p = reinterpret_cast<const float4*>(x)
                    + (size_t)b * LL * 128 + (size_t)(c * 16 + h * 8) * 128 + q;
    float4 s = make_float4(0.f, 0.f, 0.f, 0.f);
#pragma unroll
    for (int r = 0; r < 8; ++r) {
        float4 v = p[r * 128];
        s.x += v.x; s.y += v.y; s.z += v.z; s.w += v.w;
    }
    red_add_v4(&g_xsum2[h][b * DD + 4 * q], s);
}

// k2: vsum += xsum @ wv (+ L*bv on kc==0).  R13 form (LDG staging, PDL).
__global__ void k2_vsum(const float* __restrict__ wv, const float* __restrict__ bv) {
    cudaTriggerProgrammaticLaunchCompletion();
    __shared__ float4 sw[16 * 128];
    __shared__ float4 sc[256 * 4];
    float* xs = reinterpret_cast<float*>(sc);

    int t = threadIdx.x;
    int jb = blockIdx.x, kc = blockIdx.y;
    int k0 = kc * 16;

    const float4* w4 = reinterpret_cast<const float4*>(wv);
#pragma unroll
    for (int u = 0; u < 4; ++u) {
        int g = t + u * 512;
        int kk = g >> 7, jq = g & 127;
        sw[g] = w4[(size_t)(k0 + kk) * (HD / 4) + jb * 128 + jq];
    }

    cudaGridDependencySynchronize();

    if (t < 128) {
        int b = t >> 4, kk = t & 15;
        int a = b * DD + k0 + kk;
        xs[t] = g_xsum2[0][a] + g_xsum2[1][a];
    }
    __syncthreads();

    int jq = t & 127, kg = (t >> 7) & 1, bg = t >> 8;
    float4 acc[4];
#pragma unroll
    for (int i = 0; i < 4; ++i) acc[i] = make_float4(0.f, 0.f, 0.f, 0.f);
#pragma unroll
    for (int kk = 0; kk < 8; ++kk) {
        float4 wq = sw[(kg * 8 + kk) * 128 + jq];
#pragma unroll
        for (int bi = 0; bi < 4; ++bi) {
            float xv = xs[(bg * 4 + bi) * 16 + kg * 8 + kk];
            acc[bi].x += xv * wq.x; acc[bi].y += xv * wq.y;
            acc[bi].z += xv * wq.z; acc[bi].w += xv * wq.w;
        }
    }
    __syncthreads();
    int slot = (bg * 128 + jq) * 4;
    if (kg == 1) {
#pragma unroll
        for (int bi = 0; bi < 4; ++bi) sc[slot + bi] = acc[bi];
    }
    __syncthreads();
    if (kg == 0) {
        float4 lb = make_float4(0.f, 0.f, 0.f, 0.f);
        if (kc == 0) {
            float4 bv4 = reinterpret_cast<const float4*>(bv)[jb * 128 + jq];
            lb.x = 1024.f * bv4.x; lb.y = 1024.f * bv4.y;
            lb.z = 1024.f * bv4.z; lb.w = 1024.f * bv4.w;
        }
        float* base = &g_vsum4[kc & 3][0];
#pragma unroll
        for (int bi = 0; bi < 4; ++bi) {
            float4 o = sc[slot + bi];
            o.x += acc[bi].x + lb.x; o.y += acc[bi].y + lb.y;
            o.z += acc[bi].z + lb.z; o.w += acc[bi].w + lb.w;
            red_add_v4(base + (bg * 4 + bi) * HD + jb * 512 + 4 * jq, o);
        }
    }
}

// k3: zc += vsum @ fc_w (+ fc_b on jc==0).  R13 form (LDG staging, PDL).
__global__ void k3_z(const float* __restrict__ fcw, const float* __restrict__ fcb) {
    cudaTriggerProgrammaticLaunchCompletion();
    __shared__ float4 sw[16 * 128];
    __shared__ float4 sc[256 * 4];
    float* vs = reinterpret_cast<float*>(sc);

    int t = threadIdx.x;
    int jc = blockIdx.x;
    int j0 = jc * 16;

    const float4* w4 = reinterpret_cast<const float4*>(fcw);
#pragma unroll
    for (int u = 0; u < 4; ++u) {
        int g = t + u * 512;
        int jj = g >> 7, iq = g & 127;
        sw[g] = w4[(size_t)(j0 + jj) * (DD / 4) + iq];
    }

    cudaGridDependencySynchronize();

    if (t < 128) {
        int b = t >> 4, jj = t & 15;
        int a = b * HD + j0 + jj;
        vs[t] = g_vsum4[0][a] + g_vsum4[1][a] + g_vsum4[2][a] + g_vsum4[3][a];
    }
    __syncthreads();

    int iq = t & 127, jg = (t >> 7) & 1, bg = t >> 8;
    float4 acc[4];
#pragma unroll
    for (int i = 0; i < 4; ++i) acc[i] = make_float4(0.f, 0.f, 0.f, 0.f);
#pragma unroll
    for (int jj = 0; jj < 8; ++jj) {
        float4 wq = sw[(jg * 8 + jj) * 128 + iq];
#pragma unroll
        for (int bi = 0; bi < 4; ++bi) {
            float vv = vs[(bg * 4 + bi) * 16 + jg * 8 + jj];
            acc[bi].x += vv * wq.x; acc[bi].y += vv * wq.y;
            acc[bi].z += vv * wq.z; acc[bi].w += vv * wq.w;
        }
    }
    __syncthreads();
    int slot = (bg * 128 + iq) * 4;
    if (jg == 1) {
#pragma unroll
        for (int bi = 0; bi < 4; ++bi) sc[slot + bi] = acc[bi];
    }
    __syncthreads();
    if (jg == 0) {
        float4 fb = make_float4(0.f, 0.f, 0.f, 0.f);
        if (jc == 0) fb = reinterpret_cast<const float4*>(fcb)[iq];
        float* base = &g_zc[jc & 3][0];
#pragma unroll
        for (int bi = 0; bi < 4; ++bi) {
            float4 o = sc[slot + bi];
            o.x += acc[bi].x + fb.x; o.y += acc[bi].y + fb.y;
            o.z += acc[bi].z + fb.z; o.w += acc[bi].w + fb.w;
            red_add_v4(base + (bg * 4 + bi) * DD + 4 * iq, o);
        }
    }
}

// k3b: merge zc[4] -> g_z. Tiny PDL link kernel — hidden under k4's prologue.
__global__ void k3b_merge() {
    cudaTriggerProgrammaticLaunchCompletion();
    cudaGridDependencySynchronize();
    int q = blockIdx.x * 512 + threadIdx.x;
    float4 s = make_float4(0.f, 0.f, 0.f, 0.f);
#pragma unroll
    for (int c = 0; c < 4; ++c) {
        float4 v = reinterpret_cast<const float4*>(&g_zc[c][0])[q];
        s.x += v.x; s.y += v.y; s.z += v.z; s.w += v.w;
    }
    reinterpret_cast<float4*>(g_z)[q] = s;
}

// k4: out = LayerNorm(g_z[b] + x[b,l]) * g + beta.
// NEW: the block's 32 KB x tile (16 contiguous rows) arrives via ONE
// cp.async.bulk issued at entry — DMA path, zero LSU slots, transfer hides
// under the PDL wait on k3. Compute reads x from smem (LDS ~3.6x cheaper
// issue than LDG); two smem passes keep registers low.
__global__ __launch_bounds__(256, 4) void k4_ln(
        const float* __restrict__ x,
        const float* __restrict__ lng, const float* __restrict__ lnb,
        float* __restrict__ out) {
    __shared__ float4 xt[16 * 128];  // 32 KB x tile: xt[row*128 + col]
    __shared__ float4 zs[128];
    __shared__ float4 gs[128];
    __shared__ float4 bs[128];
    __shared__ unsigned long long mbar_s;
    unsigned mbar = smem_u32(&mbar_s);

    int t = threadIdx.x, blk = blockIdx.x;
    int b = blk >> 6;

    if (t == 0) mbar_init(mbar, 1);
    __syncthreads();
    if (t == 0) {
        fence_async();
        mbar_expect_tx(mbar, 32768);
        bulk_g2s(smem_u32(xt), x + (size_t)blk * 16 * DD, 32768, mbar);
    }
    if (t >= 128) {
        int u = t - 128;
        gs[u] = reinterpret_cast<const float4*>(lng)[u];
        bs[u] = reinterpret_cast<const float4*>(lnb)[u];
    }

    cudaGridDependencySynchronize();             // k3b's g_z visible

    if (t < 128)
        zs[t] = reinterpret_cast<const float4*>(g_z)[b * 128 + t];
    __syncthreads();
    mbar_wait0(mbar);                            // x tile resident

    int warp = t >> 5, lane = t & 31;
    int la = warp * 2;                           // local rows la, la+1
    const float4* xr0 = &xt[la * 128];
    const float4* xr1 = &xt[(la + 1) * 128];

    float sa = 0.f, qa = 0.f, sb = 0.f, qb = 0.f;
#pragma unroll
    for (int i = 0; i < 4; ++i) {
        float4 va = xr0[lane + 32 * i];
        float4 vb = xr1[lane + 32 * i];
        float4 z  = zs[lane + 32 * i];
        float y;
        y = va.x + z.x; sa += y; qa += y * y;
        y = va.y + z.y; sa += y; qa += y * y;
        y = va.z + z.z; sa += y; qa += y * y;
        y = va.w + z.w; sa += y; qa += y * y;
        y = vb.x + z.x; sb += y; qb += y * y;
        y = vb.y + z.y; sb += y; qb += y * y;
        y = vb.z + z.z; sb += y; qb += y * y;
        y = vb.w + z.w; sb += y; qb += y * y;
    }
#pragma unroll
    for (int o = 16; o > 0; o >>= 1) {
        sa += __shfl_xor_sync(0xFFFFFFFFu, sa, o);
        qa += __shfl_xor_sync(0xFFFFFFFFu, qa, o);
        sb += __shfl_xor_sync(0xFFFFFFFFu, sb, o);
        qb += __shfl_xor_sync(0xFFFFFFFFu, qb, o);
    }
    float mua  = sa * (1.0f / DD);
    float inva = rsqrtf(qa * (1.0f / DD) - mua * mua + 1e-5f);
    float mub  = sb * (1.0f / DD);
    float invb = rsqrtf(qb * (1.0f / DD) - mub * mub + 1e-5f);

    int row0 = blk * 16 + la;
    float4* op0 = reinterpret_cast<float4*>(out) + (size_t)row0 * 128;
    float4* op1 = op0 + 128;
#pragma unroll
    for (int i = 0; i < 4; ++i) {
        float4 va = xr0[lane + 32 * i];
        float4 vb = xr1[lane + 32 * i];
        float4 z  = zs[lane + 32 * i];
        float4 gv = gs[lane + 32 * i];
        float4 be = bs[lane + 32 * i];
        float4 o;
        o.x = (va.x + z.x - mua) * inva * gv.x + be.x;
        o.y = (va.y + z.y - mua) * inva * gv.y + be.y;
        o.z = (va.z + z.z - mua) * inva * gv.z + be.z;
        o.w = (va.w + z.w - mua) * inva * gv.w + be.w;
        op0[lane + 32 * i] = o;
        o.x = (vb.x + z.x - mub) * invb * gv.x + be.x;
        o.y = (vb.y + z.y - mub) * invb * gv.y + be.y;
        o.z = (vb.z + z.z - mub) * invb * gv.z + be.z;
        o.w = (vb.w + z.w - mub) * invb * gv.w + be.w;
        op1[lane + 32 * i] = o;
    }

    // Epilogue resets for next replay (k4 reads neither buffer).
    float4 z4 = make_float4(0.f, 0.f, 0.f, 0.f);
    if (t < 64)
        reinterpret_cast<float4*>(&g_vsum4[0][0])[blk * 64 + t] = z4;
    if (t < 4)
        reinterpret_cast<float4*>(&g_xsum2[0][0])[blk * 4 + t] = z4;
}

extern "C" void kernel_launch(void* const* d_in, const int* in_sizes, int n_in,
                              void* d_out, int out_size) {
    const float* input = (const float*)d_in[0];
    const float* wv    = (const float*)d_in[5];
    const float* bv    = (const float*)d_in[6];
    const float* fcw   = (const float*)d_in[9];
    const float* fcb   = (const float*)d_in[10];
    const float* lng   = (const float*)d_in[11];
    const float* lnb   = (const float*)d_in[12];
    float* out = (float*)d_out;

    kA<<<528, 256>>>(input);

    cudaLaunchAttribute attr[1];
    attr[0].id = cudaLaunchAttributeProgrammaticStreamSerialization;
    attr[0].val.programmaticStreamSerializationAllowed = 1;

    {
        cudaLaunchConfig_t cfg{};
        cfg.gridDim = dim3(8, 32); cfg.blockDim = dim3(512);
        cfg.attrs = attr; cfg.numAttrs = 1; cfg.stream = 0;
        cudaLaunchKernelEx(&cfg, k2_vsum, wv, bv);
    }
    {
        cudaLaunchConfig_t cfg{};
        cfg.gridDim = dim3(256); cfg.blockDim = dim3(512);
        cfg.attrs = attr; cfg.numAttrs = 1; cfg.stream = 0;
        cudaLaunchKernelEx(&cfg, k3_z, fcw, fcb);
    }
    {
        cudaLaunchConfig_t cfg{};
        cfg.gridDim = dim3(2); cfg.blockDim = dim3(512);
        cfg.attrs = attr; cfg.numAttrs = 1; cfg.stream = 0;
        cudaLaunchKernelEx(&cfg, k3b_merge);
    }
    {
        cudaLaunchConfig_t cfg{};
        cfg.gridDim = dim3(512); cfg.blockDim = dim3(256);
        cfg.attrs = attr; cfg.numAttrs = 1; cfg.stream = 0;
        cudaLaunchKernelEx(&cfg, k4_ln, input, lng, lnb, out);
    }
}

// round 16
// speedup vs baseline: 1.1608x; 1.0627x over previous
#include <cuda_runtime.h>

#define BB 8
#define LL 1024
#define DD 512
#define HD 4096

// Accumulators. Zero at module load (first call OK); k4's epilogue re-zeroes
// xsum2/vsum4 for the next replay; zc re-zeroed by kA's extra blocks each call.
__device__ __align__(16) float g_xsum2[2][BB * DD];   // 32 KB
__device__ __align__(16) float g_vsum4[4][BB * HD];   // 512 KB
__device__ __align__(16) float g_zc[4][BB * DD];      // 64 KB
__device__ __align__(16) float g_z[BB * DD];          // merged z (k3b output)

__device__ __forceinline__ void red_add_v4(float* a, float4 v) {
    asm volatile("red.global.add.v4.f32 [%0], {%1,%2,%3,%4};"
                 :: "l"(a), "f"(v.x), "f"(v.y), "f"(v.z), "f"(v.w) : "memory");
}

// kA: blocks [0,512): xsum += input over 16-row chunks (red into 2 copies).
//     blocks [512,528): zero g_zc (4096 quads) for this call.
__global__ __launch_bounds__(256) void kA(const float* __restrict__ x) {
    cudaTriggerProgrammaticLaunchCompletion();
    int blk = blockIdx.x, t = threadIdx.x;
    if (blk >= 512) {
        int q = (blk - 512) * 256 + t;
        reinterpret_cast<float4*>(&g_zc[0][0])[q] = make_float4(0.f, 0.f, 0.f, 0.f);
        return;
    }
    int b = blk >> 6, c = blk & 63;
    int h = t >> 7, q = t & 127;
    const float4* p = reinterpret_cast<const float4*>(x)
                    + (size_t)b * LL * 128 + (size_t)(c * 16 + h * 8) * 128 + q;
    float4 s = make_float4(0.f, 0.f, 0.f, 0.f);
#pragma unroll
    for (int r = 0; r < 8; ++r) {
        float4 v = p[r * 128];
        s.x += v.x; s.y += v.y; s.z += v.z; s.w += v.w;
    }
    red_add_v4(&g_xsum2[h][b * DD + 4 * q], s);
}

// k2: vsum += xsum @ wv (+ L*bv on kc==0).  R13 form (LDG staging, PDL).
__global__ void k2_vsum(const float* __restrict__ wv, const float* __restrict__ bv) {
    cudaTriggerProgrammaticLaunchCompletion();
    __shared__ float4 sw[16 * 128];
    __shared__ float4 sc[256 * 4];
    float* xs = reinterpret_cast<float*>(sc);

    int t = threadIdx.x;
    int jb = blockIdx.x, kc = blockIdx.y;
    int k0 = kc * 16;

    const float4* w4 = reinterpret_cast<const float4*>(wv);
#pragma unroll
    for (int u = 0; u < 4; ++u) {
        int g = t + u * 512;
        int kk = g >> 7, jq = g & 127;
        sw[g] = w4[(size_t)(k0 + kk) * (HD / 4) + jb * 128 + jq];
    }

    cudaGridDependencySynchronize();

    if (t < 128) {
        int b = t >> 4, kk = t & 15;
        int a = b * DD + k0 + kk;
        xs[t] = g_xsum2[0][a] + g_xsum2[1][a];
    }
    __syncthreads();

    int jq = t & 127, kg = (t >> 7) & 1, bg = t >> 8;
    float4 acc[4];
#pragma unroll
    for (int i = 0; i < 4; ++i) acc[i] = make_float4(0.f, 0.f, 0.f, 0.f);
#pragma unroll
    for (int kk = 0; kk < 8; ++kk) {
        float4 wq = sw[(kg * 8 + kk) * 128 + jq];
#pragma unroll
        for (int bi = 0; bi < 4; ++bi) {
            float xv = xs[(bg * 4 + bi) * 16 + kg * 8 + kk];
            acc[bi].x += xv * wq.x; acc[bi].y += xv * wq.y;
            acc[bi].z += xv * wq.z; acc[bi].w += xv * wq.w;
        }
    }
    __syncthreads();
    int slot = (bg * 128 + jq) * 4;
    if (kg == 1) {
#pragma unroll
        for (int bi = 0; bi < 4; ++bi) sc[slot + bi] = acc[bi];
    }
    __syncthreads();
    if (kg == 0) {
        float4 lb = make_float4(0.f, 0.f, 0.f, 0.f);
        if (kc == 0) {
            float4 bv4 = reinterpret_cast<const float4*>(bv)[jb * 128 + jq];
            lb.x = 1024.f * bv4.x; lb.y = 1024.f * bv4.y;
            lb.z = 1024.f * bv4.z; lb.w = 1024.f * bv4.w;
        }
        float* base = &g_vsum4[kc & 3][0];
#pragma unroll
        for (int bi = 0; bi < 4; ++bi) {
            float4 o = sc[slot + bi];
            o.x += acc[bi].x + lb.x; o.y += acc[bi].y + lb.y;
            o.z += acc[bi].z + lb.z; o.w += acc[bi].w + lb.w;
            red_add_v4(base + (bg * 4 + bi) * HD + jb * 512 + 4 * jq, o);
        }
    }
}

// k3: zc += vsum @ fc_w (+ fc_b on jc==0).  R13 form (LDG staging, PDL).
__global__ void k3_z(const float* __restrict__ fcw, const float* __restrict__ fcb) {
    cudaTriggerProgrammaticLaunchCompletion();
    __shared__ float4 sw[16 * 128];
    __shared__ float4 sc[256 * 4];
    float* vs = reinterpret_cast<float*>(sc);

    int t = threadIdx.x;
    int jc = blockIdx.x;
    int j0 = jc * 16;

    const float4* w4 = reinterpret_cast<const float4*>(fcw);
#pragma unroll
    for (int u = 0; u < 4; ++u) {
        int g = t + u * 512;
        int jj = g >> 7, iq = g & 127;
        sw[g] = w4[(size_t)(j0 + jj) * (DD / 4) + iq];
    }

    cudaGridDependencySynchronize();

    if (t < 128) {
        int b = t >> 4, jj = t & 15;
        int a = b * HD + j0 + jj;
        vs[t] = g_vsum4[0][a] + g_vsum4[1][a] + g_vsum4[2][a] + g_vsum4[3][a];
    }
    __syncthreads();

    int iq = t & 127, jg = (t >> 7) & 1, bg = t >> 8;
    float4 acc[4];
#pragma unroll
    for (int i = 0; i < 4; ++i) acc[i] = make_float4(0.f, 0.f, 0.f, 0.f);
#pragma unroll
    for (int jj = 0; jj < 8; ++jj) {
        float4 wq = sw[(jg * 8 + jj) * 128 + iq];
#pragma unroll
        for (int bi = 0; bi < 4; ++bi) {
            float vv = vs[(bg * 4 + bi) * 16 + jg * 8 + jj];
            acc[bi].x += vv * wq.x; acc[bi].y += vv * wq.y;
            acc[bi].z += vv * wq.z; acc[bi].w += vv * wq.w;
        }
    }
    __syncthreads();
    int slot = (bg * 128 + iq) * 4;
    if (jg == 1) {
#pragma unroll
        for (int bi = 0; bi < 4; ++bi) sc[slot + bi] = acc[bi];
    }
    __syncthreads();
    if (jg == 0) {
        float4 fb = make_float4(0.f, 0.f, 0.f, 0.f);
        if (jc == 0) fb = reinterpret_cast<const float4*>(fcb)[iq];
        float* base = &g_zc[jc & 3][0];
#pragma unroll
        for (int bi = 0; bi < 4; ++bi) {
            float4 o = sc[slot + bi];
            o.x += acc[bi].x + fb.x; o.y += acc[bi].y + fb.y;
            o.z += acc[bi].z + fb.z; o.w += acc[bi].w + fb.w;
            red_add_v4(base + (bg * 4 + bi) * DD + 4 * iq, o);
        }
    }
}

// k3b: merge zc[4] -> g_z. Tiny PDL link kernel — hidden under k4's prologue.
__global__ void k3b_merge() {
    cudaTriggerProgrammaticLaunchCompletion();
    cudaGridDependencySynchronize();
    int q = blockIdx.x * 512 + threadIdx.x;
    float4 s = make_float4(0.f, 0.f, 0.f, 0.f);
#pragma unroll
    for (int c = 0; c < 4; ++c) {
        float4 v = reinterpret_cast<const float4*>(&g_zc[c][0])[q];
        s.x += v.x; s.y += v.y; s.z += v.z; s.w += v.w;
    }
    reinterpret_cast<float4*>(g_z)[q] = s;
}

// k4: out = LayerNorm(g_z[b] + x[b,l]) * g + beta.
// REGRIDDED: 1024 blocks x 128 threads (8 rows/block, 2 rows/warp). Same
// total warps, but 2x blocks/SM -> more independent staging chains, cheaper
// 4-warp barrier, less straggler coupling. PDL prologue as in R13.
__global__ __launch_bounds__(128, 8) void k4_ln(
        const float* __restrict__ x,
        const float* __restrict__ lng, const float* __restrict__ lnb,
        float* __restrict__ out) {
    __shared__ float4 zs[128];   // merged z row for this b
    __shared__ float4 gs[128];   // ln_g
    __shared__ float4 bs[128];   // ln_b
    int t = threadIdx.x, blk = blockIdx.x;
    int b = blk >> 7;                      // 128 blocks (8 rows each) per batch

    int warp = t >> 5, lane = t & 31;
    int row0 = blk * 8 + warp * 2;
    const float4* xp0 = reinterpret_cast<const float4*>(x) + (size_t)row0 * 128;
    const float4* xp1 = xp0 + 128;

    // Independent prologue (overlaps k3 + k3b): x loads + ln params.
    float4 xa[4], xb[4];
#pragma unroll
    for (int i = 0; i < 4; ++i) xa[i] = xp0[lane + 32 * i];
#pragma unroll
    for (int i = 0; i < 4; ++i) xb[i] = xp1[lane + 32 * i];
    gs[t] = reinterpret_cast<const float4*>(lng)[t];
    bs[t] = reinterpret_cast<const float4*>(lnb)[t];

    cudaGridDependencySynchronize();             // k3b's g_z visible

    zs[t] = reinterpret_cast<const float4*>(g_z)[b * 128 + t];
    __syncthreads();

    float sa = 0.f, qa = 0.f, sb = 0.f, qb = 0.f;
#pragma unroll
    for (int i = 0; i < 4; ++i) {
        float4 z = zs[lane + 32 * i];
        float y;
        y = xa[i].x + z.x; sa += y; qa += y * y;
        y = xa[i].y + z.y; sa += y; qa += y * y;
        y = xa[i].z + z.z; sa += y; qa += y * y;
        y = xa[i].w + z.w; sa += y; qa += y * y;
        y = xb[i].x + z.x; sb += y; qb += y * y;
        y = xb[i].y + z.y; sb += y; qb += y * y;
        y = xb[i].z + z.z; sb += y; qb += y * y;
        y = xb[i].w + z.w; sb += y; qb += y * y;
    }
#pragma unroll
    for (int o = 16; o > 0; o >>= 1) {
        sa += __shfl_xor_sync(0xFFFFFFFFu, sa, o);
        qa += __shfl_xor_sync(0xFFFFFFFFu, qa, o);
        sb += __shfl_xor_sync(0xFFFFFFFFu, sb, o);
        qb += __shfl_xor_sync(0xFFFFFFFFu, qb, o);
    }
    float mua  = sa * (1.0f / DD);
    float inva = rsqrtf(qa * (1.0f / DD) - mua * mua + 1e-5f);
    float mub  = sb * (1.0f / DD);
    float invb = rsqrtf(qb * (1.0f / DD) - mub * mub + 1e-5f);

    float4* op0 = reinterpret_cast<float4*>(out) + (size_t)row0 * 128;
    float4* op1 = op0 + 128;
#pragma unroll
    for (int i = 0; i < 4; ++i) {
        float4 z  = zs[lane + 32 * i];
        float4 gv = gs[lane + 32 * i];
        float4 be = bs[lane + 32 * i];
        float4 o;
        o.x = (xa[i].x + z.x - mua) * inva * gv.x + be.x;
        o.y = (xa[i].y + z.y - mua) * inva * gv.y + be.y;
        o.z = (xa[i].z + z.z - mua) * inva * gv.z + be.z;
        o.w = (xa[i].w + z.w - mua) * inva * gv.w + be.w;
        op0[lane + 32 * i] = o;
        o.x = (xb[i].x + z.x - mub) * invb * gv.x + be.x;
        o.y = (xb[i].y + z.y - mub) * invb * gv.y + be.y;
        o.z = (xb[i].z + z.z - mub) * invb * gv.z + be.z;
        o.w = (xb[i].w + z.w - mub) * invb * gv.w + be.w;
        op1[lane + 32 * i] = o;
    }

    // Epilogue resets for next replay (k4 reads neither buffer).
    float4 z4 = make_float4(0.f, 0.f, 0.f, 0.f);
    if (t < 32)
        reinterpret_cast<float4*>(&g_vsum4[0][0])[blk * 32 + t] = z4;   // 32768 quads
    if (t < 2)
        reinterpret_cast<float4*>(&g_xsum2[0][0])[blk * 2 + t] = z4;    // 2048 quads
}

extern "C" void kernel_launch(void* const* d_in, const int* in_sizes, int n_in,
                              void* d_out, int out_size) {
    const float* input = (const float*)d_in[0];
    const float* wv    = (const float*)d_in[5];
    const float* bv    = (const float*)d_in[6];
    const float* fcw   = (const float*)d_in[9];
    const float* fcb   = (const float*)d_in[10];
    const float* lng   = (const float*)d_in[11];
    const float* lnb   = (const float*)d_in[12];
    float* out = (float*)d_out;

    kA<<<528, 256>>>(input);

    cudaLaunchAttribute attr[1];
    attr[0].id = cudaLaunchAttributeProgrammaticStreamSerialization;
    attr[0].val.programmaticStreamSerializationAllowed = 1;

    {
        cudaLaunchConfig_t cfg{};
        cfg.gridDim = dim3(8, 32); cfg.blockDim = dim3(512);
        cfg.attrs = attr; cfg.numAttrs = 1; cfg.stream = 0;
        cudaLaunchKernelEx(&cfg, k2_vsum, wv, bv);
    }
    {
        cudaLaunchConfig_t cfg{};
        cfg.gridDim = dim3(256); cfg.blockDim = dim3(512);
        cfg.attrs = attr; cfg.numAttrs = 1; cfg.stream = 0;
        cudaLaunchKernelEx(&cfg, k3_z, fcw, fcb);
    }
    {
        cudaLaunchConfig_t cfg{};
        cfg.gridDim = dim3(2); cfg.blockDim = dim3(512);
        cfg.attrs = attr; cfg.numAttrs = 1; cfg.stream = 0;
        cudaLaunchKernelEx(&cfg, k3b_merge);
    }
    {
        cudaLaunchConfig_t cfg{};
        cfg.gridDim = dim3(1024); cfg.blockDim = dim3(128);
        cfg.attrs = attr; cfg.numAttrs = 1; cfg.stream = 0;
        cudaLaunchKernelEx(&cfg, k4_ln, input, lng, lnb, out);
    }
}

// round 17
// speedup vs baseline: 1.2217x; 1.0525x over previous
#include <cuda_runtime.h>

#define BB 8
#define LL 1024
#define DD 512
#define HD 4096

// Accumulators. Zero at module load (first call OK); k4's epilogue re-zeroes
// xsum2/vsum4 for the next replay; zc re-zeroed by kA's extra blocks each call.
__device__ __align__(16) float g_xsum2[2][BB * DD];   // 32 KB
__device__ __align__(16) float g_vsum4[4][BB * HD];   // 512 KB
__device__ __align__(16) float g_zc[4][BB * DD];      // 64 KB
__device__ __align__(16) float g_z[BB * DD];          // merged z (k3b output)

__device__ __forceinline__ void red_add_v4(float* a, float4 v) {
    asm volatile("red.global.add.v4.f32 [%0], {%1,%2,%3,%4};"
                 :: "l"(a), "f"(v.x), "f"(v.y), "f"(v.z), "f"(v.w) : "memory");
}

// kA: blocks [0,512): xsum += input over 16-row chunks (red into 2 copies).
//     blocks [512,528): zero g_zc (4096 quads) for this call.
__global__ __launch_bounds__(256) void kA(const float* __restrict__ x) {
    cudaTriggerProgrammaticLaunchCompletion();
    int blk = blockIdx.x, t = threadIdx.x;
    if (blk >= 512) {
        int q = (blk - 512) * 256 + t;
        reinterpret_cast<float4*>(&g_zc[0][0])[q] = make_float4(0.f, 0.f, 0.f, 0.f);
        return;
    }
    int b = blk >> 6, c = blk & 63;
    int h = t >> 7, q = t & 127;
    const float4* p = reinterpret_cast<const float4*>(x)
                    + (size_t)b * LL * 128 + (size_t)(c * 16 + h * 8) * 128 + q;
    float4 s = make_float4(0.f, 0.f, 0.f, 0.f);
#pragma unroll
    for (int r = 0; r < 8; ++r) {
        float4 v = p[r * 128];
        s.x += v.x; s.y += v.y; s.z += v.z; s.w += v.w;
    }
    red_add_v4(&g_xsum2[h][b * DD + 4 * q], s);
}

// k2: vsum += xsum @ wv (+ L*bv on kc==0).  LDG weight staging overlaps kA
// via PDL; gridDependencySynchronize before the xsum read.
__global__ void k2_vsum(const float* __restrict__ wv, const float* __restrict__ bv) {
    cudaTriggerProgrammaticLaunchCompletion();
    __shared__ float4 sw[16 * 128];   // 32 KB
    __shared__ float4 sc[256 * 4];    // 16 KB; first 512 B doubles as xs
    float* xs = reinterpret_cast<float*>(sc);

    int t = threadIdx.x;
    int jb = blockIdx.x, kc = blockIdx.y;
    int k0 = kc * 16;

    const float4* w4 = reinterpret_cast<const float4*>(wv);
#pragma unroll
    for (int u = 0; u < 4; ++u) {
        int g = t + u * 512;
        int kk = g >> 7, jq = g & 127;
        sw[g] = w4[(size_t)(k0 + kk) * (HD / 4) + jb * 128 + jq];
    }

    cudaGridDependencySynchronize();

    if (t < 128) {
        int b = t >> 4, kk = t & 15;
        int a = b * DD + k0 + kk;
        xs[t] = g_xsum2[0][a] + g_xsum2[1][a];
    }
    __syncthreads();

    int jq = t & 127, kg = (t >> 7) & 1, bg = t >> 8;
    float4 acc[4];
#pragma unroll
    for (int i = 0; i < 4; ++i) acc[i] = make_float4(0.f, 0.f, 0.f, 0.f);
#pragma unroll
    for (int kk = 0; kk < 8; ++kk) {
        float4 wq = sw[(kg * 8 + kk) * 128 + jq];
#pragma unroll
        for (int bi = 0; bi < 4; ++bi) {
            float xv = xs[(bg * 4 + bi) * 16 + kg * 8 + kk];
            acc[bi].x += xv * wq.x; acc[bi].y += xv * wq.y;
            acc[bi].z += xv * wq.z; acc[bi].w += xv * wq.w;
        }
    }
    __syncthreads();
    int slot = (bg * 128 + jq) * 4;
    if (kg == 1) {
#pragma unroll
        for (int bi = 0; bi < 4; ++bi) sc[slot + bi] = acc[bi];
    }
    __syncthreads();
    if (kg == 0) {
        float4 lb = make_float4(0.f, 0.f, 0.f, 0.f);
        if (kc == 0) {
            float4 bv4 = reinterpret_cast<const float4*>(bv)[jb * 128 + jq];
            lb.x = 1024.f * bv4.x; lb.y = 1024.f * bv4.y;
            lb.z = 1024.f * bv4.z; lb.w = 1024.f * bv4.w;
        }
        float* base = &g_vsum4[kc & 3][0];
#pragma unroll
        for (int bi = 0; bi < 4; ++bi) {
            float4 o = sc[slot + bi];
            o.x += acc[bi].x + lb.x; o.y += acc[bi].y + lb.y;
            o.z += acc[bi].z + lb.z; o.w += acc[bi].w + lb.w;
            red_add_v4(base + (bg * 4 + bi) * HD + jb * 512 + 4 * jq, o);
        }
    }
}

// k3: zc += vsum @ fc_w (+ fc_b on jc==0).  LDG weight staging overlaps k2.
__global__ void k3_z(const float* __restrict__ fcw, const float* __restrict__ fcb) {
    cudaTriggerProgrammaticLaunchCompletion();
    __shared__ float4 sw[16 * 128];
    __shared__ float4 sc[256 * 4];
    float* vs = reinterpret_cast<float*>(sc);

    int t = threadIdx.x;
    int jc = blockIdx.x;
    int j0 = jc * 16;

    const float4* w4 = reinterpret_cast<const float4*>(fcw);
#pragma unroll
    for (int u = 0; u < 4; ++u) {
        int g = t + u * 512;
        int jj = g >> 7, iq = g & 127;
        sw[g] = w4[(size_t)(j0 + jj) * (DD / 4) + iq];
    }

    cudaGridDependencySynchronize();

    if (t < 128) {
        int b = t >> 4, jj = t & 15;
        int a = b * HD + j0 + jj;
        vs[t] = g_vsum4[0][a] + g_vsum4[1][a] + g_vsum4[2][a] + g_vsum4[3][a];
    }
    __syncthreads();

    int iq = t & 127, jg = (t >> 7) & 1, bg = t >> 8;
    float4 acc[4];
#pragma unroll
    for (int i = 0; i < 4; ++i) acc[i] = make_float4(0.f, 0.f, 0.f, 0.f);
#pragma unroll
    for (int jj = 0; jj < 8; ++jj) {
        float4 wq = sw[(jg * 8 + jj) * 128 + iq];
#pragma unroll
        for (int bi = 0; bi < 4; ++bi) {
            float vv = vs[(bg * 4 + bi) * 16 + jg * 8 + jj];
            acc[bi].x += vv * wq.x; acc[bi].y += vv * wq.y;
            acc[bi].z += vv * wq.z; acc[bi].w += vv * wq.w;
        }
    }
    __syncthreads();
    int slot = (bg * 128 + iq) * 4;
    if (jg == 1) {
#pragma unroll
        for (int bi = 0; bi < 4; ++bi) sc[slot + bi] = acc[bi];
    }
    __syncthreads();
    if (jg == 0) {
        float4 fb = make_float4(0.f, 0.f, 0.f, 0.f);
        if (jc == 0) fb = reinterpret_cast<const float4*>(fcb)[iq];
        float* base = &g_zc[jc & 3][0];
#pragma unroll
        for (int bi = 0; bi < 4; ++bi) {
            float4 o = sc[slot + bi];
            o.x += acc[bi].x + fb.x; o.y += acc[bi].y + fb.y;
            o.z += acc[bi].z + fb.z; o.w += acc[bi].w + fb.w;
            red_add_v4(base + (bg * 4 + bi) * DD + 4 * iq, o);
        }
    }
}

// k3b: merge zc[4] -> g_z. Tiny PDL link kernel — hidden under k4's prologue.
__global__ void k3b_merge() {
    cudaTriggerProgrammaticLaunchCompletion();
    cudaGridDependencySynchronize();
    int q = blockIdx.x * 512 + threadIdx.x;      // 1024 quads / 2 blocks
    float4 s = make_float4(0.f, 0.f, 0.f, 0.f);
#pragma unroll
    for (int c = 0; c < 4; ++c) {
        float4 v = reinterpret_cast<const float4*>(&g_zc[c][0])[q];
        s.x += v.x; s.y += v.y; s.z += v.z; s.w += v.w;
    }
    reinterpret_cast<float4*>(g_z)[q] = s;
}

// k4: out = LayerNorm(g_z[b] + x[b,l]) * g + beta.  512 blocks x 256 threads,
// two rows per warp; PDL prologue (x loads + ln params) overlaps k3/k3b;
// post-sync z stage is ONE load. Epilogue resets for next replay.
__global__ __launch_bounds__(256, 4) void k4_ln(
        const float* __restrict__ x,
        const float* __restrict__ lng, const float* __restrict__ lnb,
        float* __restrict__ out) {
    __shared__ float4 zs[128];
    __shared__ float4 gs[128];
    __shared__ float4 bs[128];
    int t = threadIdx.x, blk = blockIdx.x;
    int b = blk >> 6;

    int warp = t >> 5, lane = t & 31;
    int row0 = blk * 16 + warp * 2;
    const float4* xp0 = reinterpret_cast<const float4*>(x) + (size_t)row0 * 128;
    const float4* xp1 = xp0 + 128;

    float4 xa[4], xb[4];
#pragma unroll
    for (int i = 0; i < 4; ++i) xa[i] = xp0[lane + 32 * i];
#pragma unroll
    for (int i = 0; i < 4; ++i) xb[i] = xp1[lane + 32 * i];
    if (t >= 128) {
        int u = t - 128;
        gs[u] = reinterpret_cast<const float4*>(lng)[u];
        bs[u] = reinterpret_cast<const float4*>(lnb)[u];
    }

    cudaGridDependencySynchronize();

    if (t < 128)
        zs[t] = reinterpret_cast<const float4*>(g_z)[b * 128 + t];
    __syncthreads();

    float sa = 0.f, qa = 0.f, sb = 0.f, qb = 0.f;
#pragma unroll
    for (int i = 0; i < 4; ++i) {
        float4 z = zs[lane + 32 * i];
        float y;
        y = xa[i].x + z.x; sa += y; qa += y * y;
        y = xa[i].y + z.y; sa += y; qa += y * y;
        y = xa[i].z + z.z; sa += y; qa += y * y;
        y = xa[i].w + z.w; sa += y; qa += y * y;
        y = xb[i].x + z.x; sb += y; qb += y * y;
        y = xb[i].y + z.y; sb += y; qb += y * y;
        y = xb[i].z + z.z; sb += y; qb += y * y;
        y = xb[i].w + z.w; sb += y; qb += y * y;
    }
#pragma unroll
    for (int o = 16; o > 0; o >>= 1) {
        sa += __shfl_xor_sync(0xFFFFFFFFu, sa, o);
        qa += __shfl_xor_sync(0xFFFFFFFFu, qa, o);
        sb += __shfl_xor_sync(0xFFFFFFFFu, sb, o);
        qb += __shfl_xor_sync(0xFFFFFFFFu, qb, o);
    }
    float mua  = sa * (1.0f / DD);
    float inva = rsqrtf(qa * (1.0f / DD) - mua * mua + 1e-5f);
    float mub  = sb * (1.0f / DD);
    float invb = rsqrtf(qb * (1.0f / DD) - mub * mub + 1e-5f);

    float4* op0 = reinterpret_cast<float4*>(out) + (size_t)row0 * 128;
    float4* op1 = op0 + 128;
#pragma unroll
    for (int i = 0; i < 4; ++i) {
        float4 z  = zs[lane + 32 * i];
        float4 gv = gs[lane + 32 * i];
        float4 be = bs[lane + 32 * i];
        float4 o;
        o.x = (xa[i].x + z.x - mua) * inva * gv.x + be.x;
        o.y = (xa[i].y + z.y - mua) * inva * gv.y + be.y;
        o.z = (xa[i].z + z.z - mua) * inva * gv.z + be.z;
        o.w = (xa[i].w + z.w - mua) * inva * gv.w + be.w;
        op0[lane + 32 * i] = o;
        o.x = (xb[i].x + z.x - mub) * invb * gv.x + be.x;
        o.y = (xb[i].y + z.y - mub) * invb * gv.y + be.y;
        o.z = (xb[i].z + z.z - mub) * invb * gv.z + be.z;
        o.w = (xb[i].w + z.w - mub) * invb * gv.w + be.w;
        op1[lane + 32 * i] = o;
    }

    // Epilogue resets for next replay (k4 reads neither buffer).
    float4 z4 = make_float4(0.f, 0.f, 0.f, 0.f);
    if (t < 64)
        reinterpret_cast<float4*>(&g_vsum4[0][0])[blk * 64 + t] = z4;
    if (t < 4)
        reinterpret_cast<float4*>(&g_xsum2[0][0])[blk * 4 + t] = z4;
}

extern "C" void kernel_launch(void* const* d_in, const int* in_sizes, int n_in,
                              void* d_out, int out_size) {
    const float* input = (const float*)d_in[0];
    const float* wv    = (const float*)d_in[5];
    const float* bv    = (const float*)d_in[6];
    const float* fcw   = (const float*)d_in[9];
    const float* fcb   = (const float*)d_in[10];
    const float* lng   = (const float*)d_in[11];
    const float* lnb   = (const float*)d_in[12];
    float* out = (float*)d_out;

    kA<<<528, 256>>>(input);

    cudaLaunchAttribute attr[1];
    attr[0].id = cudaLaunchAttributeProgrammaticStreamSerialization;
    attr[0].val.programmaticStreamSerializationAllowed = 1;

    {
        cudaLaunchConfig_t cfg{};
        cfg.gridDim = dim3(8, 32); cfg.blockDim = dim3(512);
        cfg.attrs = attr; cfg.numAttrs = 1; cfg.stream = 0;
        cudaLaunchKernelEx(&cfg, k2_vsum, wv, bv);
    }
    {
        cudaLaunchConfig_t cfg{};
        cfg.gridDim = dim3(256); cfg.blockDim = dim3(512);
        cfg.attrs = attr; cfg.numAttrs = 1; cfg.stream = 0;
        cudaLaunchKernelEx(&cfg, k3_z, fcw, fcb);
    }
    {
        cudaLaunchConfig_t cfg{};
        cfg.gridDim = dim3(2); cfg.blockDim = dim3(512);
        cfg.attrs = attr; cfg.numAttrs = 1; cfg.stream = 0;
        cudaLaunchKernelEx(&cfg, k3b_merge);
    }
    {
        cudaLaunchConfig_t cfg{};
        cfg.gridDim = dim3(512); cfg.blockDim = dim3(256);
        cfg.attrs = attr; cfg.numAttrs = 1; cfg.stream = 0;
        cudaLaunchKernelEx(&cfg, k4_ln, input, lng, lnb, out);
    }
}